// round 8
// baseline (speedup 1.0000x reference)
#include <cuda_runtime.h>
#include <math.h>
#include <stdint.h>

#define N_ROWS 100000
#define HIDDEN 256
#define NCLASS 64
#define TAU_F 1.0f
#define BN_EPS 1e-5f

#define BM 128
#define BK 32
#define THREADS 512
#define AS_STRIDE 36
#define BS_STRIDE 264
#define HS_STRIDE 132
#define WS_STRIDE 68

// double-buffered mainloop smem (floats):
//   As0 @0 (4608), Bs0 @4608 (8448), As1 @13056 (4608), Bs1 @17664 (8448)
// epilogue aliases: sh_h @0 (16896), sh_w @16896 (8704)
#define A0_OFF 0
#define B0_OFF 4608
#define A1_OFF 13056
#define B1_OFF 17664
#define WS_OFF 16896
#define SMEM_BYTES 104448

#define NT_COLS 192     // tensor-covered columns; FFMA covers [192,256)

// ---------------- device scratch ----------------
__device__ float g_probs[8];
__device__ float g_sum[NCLASS];
__device__ float g_ssq[NCLASS];

struct GemmParams {
    const float* A[8];   // feat0..5, lab0, lab1   [N, d]
    const float* B[8];   // emb0..5, lemb0, lemb1  [d, 256]
    int d[8];
};

__device__ __forceinline__ float f2tf32(float x) {
    uint32_t u;
    asm("cvt.rna.tf32.f32 %0, %1;" : "=r"(u) : "f"(x));
    return __uint_as_float(u);
}

// ---------------- kernel 0: gumbel-softmax gate + zero BN stats ----------------
__global__ void probs_kernel(const float* __restrict__ alpha,
                             const float* __restrict__ gumbels,
                             const int* __restrict__ es) {
    int t = threadIdx.x;
    if (t < NCLASS) { g_sum[t] = 0.f; g_ssq[t] = 0.f; }
    if (t == 0) {
        float ws[8];
        float m = -1e30f;
        #pragma unroll
        for (int i = 0; i < 8; i++) { ws[i] = alpha[es[i]]; m = fmaxf(m, ws[i]); }
        float se = 0.f;
        #pragma unroll
        for (int i = 0; i < 8; i++) se += expf(ws[i] - m);
        float lse = m + logf(se);
        float lg[8];
        float m2 = -1e30f;
        #pragma unroll
        for (int i = 0; i < 8; i++) {
            lg[i] = (ws[i] - lse + gumbels[i]) / TAU_F;
            m2 = fmaxf(m2, lg[i]);
        }
        float s2 = 0.f;
        #pragma unroll
        for (int i = 0; i < 8; i++) { lg[i] = expf(lg[i] - m2); s2 += lg[i]; }
        #pragma unroll
        for (int i = 0; i < 8; i++) g_probs[i] = lg[i] / s2;
    }
}

// ------ kernel 1: hybrid tensor+FFMA segmented GEMM + PReLU + GEMM2 + stats ----
__global__ __launch_bounds__(THREADS, 1)
void gemm1_kernel(GemmParams p, const float* __restrict__ prelu_ptr,
                  const float* __restrict__ w_out, float* __restrict__ z) {
    extern __shared__ float smem[];
    float* sh_h = smem;               // epilogue [128][132]
    float* sh_w = smem + WS_OFF;      // epilogue [128][68]

    __shared__ float s_sum[NCLASS];
    __shared__ float s_ssq[NCLASS];

    const int tid = threadIdx.x;
    const int wid = tid >> 5, lane = tid & 31;
    const bool is_tensor = (wid < 12);
    // tensor warp grid: 2 x 6 (rows wm*64, cols wn*32 in [0,192))
    const int wm = wid / 6, wn = wid % 6;
    const int g = lane >> 2, t4 = lane & 3;
    // FFMA warps (wid 12..15): one row per thread, cols [192,256)
    const int ffrow = (wid - 12) * 32 + lane;
    const int row0 = blockIdx.x * BM;

    if (tid < NCLASS) { s_sum[tid] = 0.f; s_ssq[tid] = 0.f; }

    // 64 accumulators, shared storage between roles:
    //   tensor: acc[((t*4)+u)*4 + i]   (4 row-tiles x 4 col-tiles x 4)
    //   ffma:   acc[q*4 + j]           (16 quads of 4 columns)
    float acc[64];
    #pragma unroll
    for (int i = 0; i < 64; i++) acc[i] = 0.f;

    // staging registers (prefetch distance: 2 chunks)
    float  ra[8];
    float4 rb[4];

    const int a_off[2] = {A0_OFF, A1_OFF};
    const int b_off[2] = {B0_OFF, B1_OFF};

    auto load_regs = [&](int cs, int k0) {
        const float* __restrict__ A = p.A[cs];
        const float* __restrict__ B = p.B[cs];
        const int d = p.d[cs];
        const float pc = g_probs[cs];
        const int ka = k0 + (tid & 31);
        const int rbase = tid >> 5;
        const bool kok = (ka < d);
        #pragma unroll
        for (int l = 0; l < 8; l++) {
            int row = row0 + rbase + l * 16;
            ra[l] = (kok && row < N_ROWS) ? A[(long)row * d + ka] : 0.f;
        }
        #pragma unroll
        for (int l = 0; l < 4; l++) {
            int flat = l * THREADS + tid;
            int kk = flat >> 6, n4 = flat & 63;
            int k = k0 + kk;
            float4 v = make_float4(0.f, 0.f, 0.f, 0.f);
            if (k < d) v = *(const float4*)(B + (long)k * HIDDEN + n4 * 4);
            v.x *= pc; v.y *= pc; v.z *= pc; v.w *= pc;
            rb[l] = v;
        }
    };

    auto store_tiles = [&](int buf) {
        float* As = smem + a_off[buf];
        float* Bs = smem + b_off[buf];
        const int rbase = tid >> 5;
        const int ka = tid & 31;
        #pragma unroll
        for (int l = 0; l < 8; l++)
            As[(rbase + l * 16) * AS_STRIDE + ka] = f2tf32(ra[l]);
        #pragma unroll
        for (int l = 0; l < 4; l++) {
            int flat = l * THREADS + tid;
            int kk = flat >> 6, n4 = flat & 63;
            float4 v = rb[l];
            float4 w4 = make_float4(f2tf32(v.x), f2tf32(v.y), f2tf32(v.z), f2tf32(v.w));
            *(float4*)&Bs[kk * BS_STRIDE + n4 * 4] = w4;
        }
    };

    auto compute_tensor = [&](int buf) {
        const float* As = smem + a_off[buf];
        const float* Bs = smem + b_off[buf];
        #pragma unroll
        for (int ks = 0; ks < 4; ks++) {
            const int kk = ks * 8;
            uint32_t a[4][4];
            #pragma unroll
            for (int t = 0; t < 4; t++) {
                int base = (wm * 64 + t * 16 + g) * AS_STRIDE + kk + t4;
                a[t][0] = __float_as_uint(As[base]);
                a[t][1] = __float_as_uint(As[base + 8 * AS_STRIDE]);
                a[t][2] = __float_as_uint(As[base + 4]);
                a[t][3] = __float_as_uint(As[base + 8 * AS_STRIDE + 4]);
            }
            uint32_t b[4][2];
            #pragma unroll
            for (int u = 0; u < 4; u++) {
                int base = (kk + t4) * BS_STRIDE + wn * 32 + u * 8 + g;
                b[u][0] = __float_as_uint(Bs[base]);
                b[u][1] = __float_as_uint(Bs[base + 4 * BS_STRIDE]);
            }
            #pragma unroll
            for (int t = 0; t < 4; t++)
                #pragma unroll
                for (int u = 0; u < 4; u++)
                    asm volatile(
                        "mma.sync.aligned.m16n8k8.row.col.f32.tf32.tf32.f32 "
                        "{%0,%1,%2,%3}, {%4,%5,%6,%7}, {%8,%9}, {%0,%1,%2,%3};\n"
                        : "+f"(acc[(t * 4 + u) * 4 + 0]), "+f"(acc[(t * 4 + u) * 4 + 1]),
                          "+f"(acc[(t * 4 + u) * 4 + 2]), "+f"(acc[(t * 4 + u) * 4 + 3])
                        : "r"(a[t][0]), "r"(a[t][1]), "r"(a[t][2]), "r"(a[t][3]),
                          "r"(b[u][0]), "r"(b[u][1]));
        }
    };

    auto compute_ffma = [&](int buf) {
        const float* As = smem + a_off[buf];
        const float* Bs = smem + b_off[buf];
        const float* arow = As + ffrow * AS_STRIDE;
        #pragma unroll 2
        for (int k4 = 0; k4 < 8; k4++) {
            float4 a4 = *(const float4*)&arow[k4 * 4];
            #pragma unroll
            for (int kj = 0; kj < 4; kj++) {
                float a = (kj == 0) ? a4.x : (kj == 1) ? a4.y : (kj == 2) ? a4.z : a4.w;
                const float* brow = Bs + (k4 * 4 + kj) * BS_STRIDE + NT_COLS;
                #pragma unroll
                for (int q = 0; q < 16; q++) {
                    float4 b = *(const float4*)&brow[q * 4];   // warp-uniform (broadcast)
                    acc[q * 4 + 0] = fmaf(a, b.x, acc[q * 4 + 0]);
                    acc[q * 4 + 1] = fmaf(a, b.y, acc[q * 4 + 1]);
                    acc[q * 4 + 2] = fmaf(a, b.z, acc[q * 4 + 2]);
                    acc[q * 4 + 3] = fmaf(a, b.w, acc[q * 4 + 3]);
                }
            }
        }
    };

    // -------- mainloop: double-buffered, one __syncthreads per chunk --------
    int total = 0;
    #pragma unroll
    for (int c = 0; c < 8; c++) total += (p.d[c] + BK - 1) / BK;   // 86

    int lcs = 0, lk0 = 0;                 // load cursor
    auto advance = [&]() { lk0 += BK; if (lk0 >= p.d[lcs]) { lk0 = 0; ++lcs; } };

    load_regs(lcs, lk0);                  // chunk 0
    store_tiles(0);
    advance();
    if (1 < total) load_regs(lcs, lk0);   // chunk 1
    __syncthreads();

    for (int chunk = 0;; chunk++) {
        const int buf = chunk & 1;
        const bool have_next = (chunk + 1 < total);
        if (have_next) {
            store_tiles(buf ^ 1);         // regs of chunk+1 -> other buffer
            advance();
            if (chunk + 2 < total) load_regs(lcs, lk0);   // prefetch chunk+2
        }
        if (is_tensor) compute_tensor(buf);
        else           compute_ffma(buf);
        __syncthreads();
        if (!have_next) break;
    }

    // -------- epilogue: PReLU + z = h @ w_out^T (two 128-col K halves) --------
    const float pa = *prelu_ptr;
    float accz[4][4];
    #pragma unroll
    for (int i = 0; i < 4; i++)
        #pragma unroll
        for (int j = 0; j < 4; j++) accz[i][j] = 0.f;

    const int rg = tid >> 4;   // 0..31 -> rows rg*4..+3
    const int cg = tid & 15;   // 0..15 -> classes cg*4..+3

    #pragma unroll
    for (int kh = 0; kh < 2; kh++) {
        if (is_tensor) {
            // tensor warps stage their 32-col slab when it falls in this half:
            // kh=0: wn 0..3 -> cols 0..127 ; kh=1: wn 4,5 -> cols 128..191
            const bool mine = (kh == 0) ? (wn < 4) : (wn >= 4);
            if (mine) {
                const int cbase = (kh == 0) ? wn * 32 : (wn - 4) * 32;
                #pragma unroll
                for (int t = 0; t < 4; t++) {
                    const int r1 = wm * 64 + t * 16 + g;
                    #pragma unroll
                    for (int u = 0; u < 4; u++) {
                        const int col = cbase + u * 8 + t4 * 2;
                        float x0 = acc[(t * 4 + u) * 4 + 0], x1 = acc[(t * 4 + u) * 4 + 1];
                        float x2 = acc[(t * 4 + u) * 4 + 2], x3 = acc[(t * 4 + u) * 4 + 3];
                        float2 h01 = make_float2(x0 >= 0.f ? x0 : pa * x0,
                                                 x1 >= 0.f ? x1 : pa * x1);
                        float2 h23 = make_float2(x2 >= 0.f ? x2 : pa * x2,
                                                 x3 >= 0.f ? x3 : pa * x3);
                        *(float2*)&sh_h[r1 * HS_STRIDE + col] = h01;
                        *(float2*)&sh_h[(r1 + 8) * HS_STRIDE + col] = h23;
                    }
                }
            }
        } else if (kh == 1) {
            // FFMA warps own global cols 192..255 -> local cols 64..127 of half 1
            #pragma unroll
            for (int q = 0; q < 16; q++) {
                float x0 = acc[q * 4 + 0], x1 = acc[q * 4 + 1];
                float x2 = acc[q * 4 + 2], x3 = acc[q * 4 + 3];
                float4 v;
                v.x = (x0 >= 0.f) ? x0 : pa * x0;
                v.y = (x1 >= 0.f) ? x1 : pa * x1;
                v.z = (x2 >= 0.f) ? x2 : pa * x2;
                v.w = (x3 >= 0.f) ? x3 : pa * x3;
                *(float4*)&sh_h[ffrow * HS_STRIDE + 64 + q * 4] = v;
            }
        }
        // stage w_out[:, kh*128 : +128] k-major into smem
        #pragma unroll
        for (int l = 0; l < 4; l++) {
            int flat = l * THREADS + tid;
            int c = flat & 63, kq = flat >> 6;
            float4 wv = *(const float4*)(w_out + (long)c * HIDDEN + kh * 128 + kq * 4);
            sh_w[(kq * 4 + 0) * WS_STRIDE + c] = wv.x;
            sh_w[(kq * 4 + 1) * WS_STRIDE + c] = wv.y;
            sh_w[(kq * 4 + 2) * WS_STRIDE + c] = wv.z;
            sh_w[(kq * 4 + 3) * WS_STRIDE + c] = wv.w;
        }
        __syncthreads();
        #pragma unroll 8
        for (int k = 0; k < 128; k++) {
            float a0 = sh_h[(rg * 4 + 0) * HS_STRIDE + k];
            float a1 = sh_h[(rg * 4 + 1) * HS_STRIDE + k];
            float a2 = sh_h[(rg * 4 + 2) * HS_STRIDE + k];
            float a3 = sh_h[(rg * 4 + 3) * HS_STRIDE + k];
            float4 wv = *(float4*)&sh_w[k * WS_STRIDE + cg * 4];
            accz[0][0] = fmaf(a0, wv.x, accz[0][0]);
            accz[0][1] = fmaf(a0, wv.y, accz[0][1]);
            accz[0][2] = fmaf(a0, wv.z, accz[0][2]);
            accz[0][3] = fmaf(a0, wv.w, accz[0][3]);
            accz[1][0] = fmaf(a1, wv.x, accz[1][0]);
            accz[1][1] = fmaf(a1, wv.y, accz[1][1]);
            accz[1][2] = fmaf(a1, wv.z, accz[1][2]);
            accz[1][3] = fmaf(a1, wv.w, accz[1][3]);
            accz[2][0] = fmaf(a2, wv.x, accz[2][0]);
            accz[2][1] = fmaf(a2, wv.y, accz[2][1]);
            accz[2][2] = fmaf(a2, wv.z, accz[2][2]);
            accz[2][3] = fmaf(a2, wv.w, accz[2][3]);
            accz[3][0] = fmaf(a3, wv.x, accz[3][0]);
            accz[3][1] = fmaf(a3, wv.y, accz[3][1]);
            accz[3][2] = fmaf(a3, wv.z, accz[3][2]);
            accz[3][3] = fmaf(a3, wv.w, accz[3][3]);
        }
        __syncthreads();
    }

    // -------- write z + BN partial stats --------
    float s[4] = {0.f, 0.f, 0.f, 0.f};
    float q[4] = {0.f, 0.f, 0.f, 0.f};
    #pragma unroll
    for (int i = 0; i < 4; i++) {
        int row = row0 + rg * 4 + i;
        if (row < N_ROWS) {
            float4 v = make_float4(accz[i][0], accz[i][1], accz[i][2], accz[i][3]);
            *(float4*)&z[(long)row * NCLASS + cg * 4] = v;
            s[0] += v.x; q[0] += v.x * v.x;
            s[1] += v.y; q[1] += v.y * v.y;
            s[2] += v.z; q[2] += v.z * v.z;
            s[3] += v.w; q[3] += v.w * v.w;
        }
    }
    #pragma unroll
    for (int j = 0; j < 4; j++) {
        atomicAdd(&s_sum[cg * 4 + j], s[j]);
        atomicAdd(&s_ssq[cg * 4 + j], q[j]);
    }
    __syncthreads();
    if (tid < NCLASS) {
        atomicAdd(&g_sum[tid], s_sum[tid]);
        atomicAdd(&g_ssq[tid], s_ssq[tid]);
    }
}

// ---------------- kernel 2: batchnorm normalize in place ----------------
__global__ __launch_bounds__(256) void bn_kernel(float* __restrict__ z) {
    __shared__ float mean_s[NCLASS];
    __shared__ float rstd_s[NCLASS];
    int t = threadIdx.x;
    if (t < NCLASS) {
        float m = g_sum[t] * (1.0f / (float)N_ROWS);
        float v = g_ssq[t] * (1.0f / (float)N_ROWS) - m * m;
        mean_s[t] = m;
        rstd_s[t] = rsqrtf(v + BN_EPS);
    }
    __syncthreads();
    const size_t nq = (size_t)N_ROWS * NCLASS / 4;
    const size_t stride = (size_t)gridDim.x * blockDim.x;
    size_t i0 = (size_t)blockIdx.x * blockDim.x + t;
    int c = (int)((i0 * 4) & (NCLASS - 1));
    float m0 = mean_s[c], m1 = mean_s[c + 1], m2 = mean_s[c + 2], m3 = mean_s[c + 3];
    float r0 = rstd_s[c], r1 = rstd_s[c + 1], r2 = rstd_s[c + 2], r3 = rstd_s[c + 3];
    for (size_t i = i0; i < nq; i += stride) {
        float4 v = ((float4*)z)[i];
        v.x = (v.x - m0) * r0;
        v.y = (v.y - m1) * r1;
        v.z = (v.z - m2) * r2;
        v.w = (v.w - m3) * r3;
        ((float4*)z)[i] = v;
    }
}

// ---------------- host launcher ----------------
extern "C" void kernel_launch(void* const* d_in, const int* in_sizes, int n_in,
                              void* d_out, int out_size) {
    static const long dims[6] = {334, 512, 128, 745, 256, 600};
    const float* feat[8] = {0};
    const float* emb[8]  = {0};
    const float* alpha = 0;
    const float* gumbels = 0;
    const float* prelu_a = 0;
    const float* w_out = 0;
    const int* es = 0;
    int labc = 0, l16 = 0, c8 = 0;

    for (int i = 0; i < n_in; i++) {
        long s = (long)in_sizes[i];
        const void* ptr = d_in[i];
        bool matched = false;
        for (int k = 0; k < 6; k++) {
            if (s == 100000L * dims[k] && !feat[k]) { feat[k] = (const float*)ptr; matched = true; break; }
            if (s == dims[k] * 256L    && !emb[k])  { emb[k]  = (const float*)ptr; matched = true; break; }
        }
        if (matched) continue;
        if (s == 6400000L) {
            if (labc < 2) feat[6 + labc] = (const float*)ptr;
            labc++;
        } else if (s == 16384L) {
            if (l16 < 2) emb[6 + l16] = (const float*)ptr;
            else w_out = (const float*)ptr;
            l16++;
        } else if (s == 8L) {
            if (c8 == 0) alpha = (const float*)ptr;
            else if (c8 == 1) gumbels = (const float*)ptr;
            else es = (const int*)ptr;
            c8++;
        } else if (s == 1L) {
            prelu_a = (const float*)ptr;
        }
    }

    GemmParams gp;
    for (int c = 0; c < 8; c++) {
        gp.A[c] = feat[c];
        gp.B[c] = emb[c];
        gp.d[c] = (c < 6) ? (int)dims[c] : NCLASS;
    }

    float* z = (float*)d_out;
    const int grid1 = (N_ROWS + BM - 1) / BM;   // 782

    static int attr_set = 0;
    if (!attr_set) {
        cudaFuncSetAttribute(gemm1_kernel,
                             cudaFuncAttributeMaxDynamicSharedMemorySize, SMEM_BYTES);
        attr_set = 1;
    }

    probs_kernel<<<1, 128>>>(alpha, gumbels, es);
    gemm1_kernel<<<grid1, THREADS, SMEM_BYTES>>>(gp, prelu_a, w_out, z);
    bn_kernel<<<1024, 256>>>(z);
}

// round 9
// speedup vs baseline: 1.4945x; 1.4945x over previous
#include <cuda_runtime.h>
#include <math.h>
#include <stdint.h>

#define N_ROWS 100000
#define HIDDEN 256
#define NCLASS 64
#define TAU_F 1.0f
#define BN_EPS 1e-5f

#define BM 128
#define BK 32
#define THREADS 512
#define AS_STRIDE 36
#define BS_STRIDE 264
#define HS_STRIDE 132
#define WS_STRIDE 68

#define A0_OFF 0
#define B0_OFF 4608
#define A1_OFF 13056
#define B1_OFF 17664
#define WS_OFF 16896
#define SMEM_BYTES 104448

#define NT_COLS 192     // tensor-covered columns; FFMA covers [192,256)

// ---------------- device scratch ----------------
__device__ float g_probs[8];
__device__ float g_sum[NCLASS];
__device__ float g_ssq[NCLASS];

struct GemmParams {
    const float* A[8];   // feat0..5, lab0, lab1   [N, d]
    const float* B[8];   // emb0..5, lemb0, lemb1  [d, 256]
    int d[8];
};

__device__ __forceinline__ float f2tf32(float x) {
    uint32_t u;
    asm("cvt.rna.tf32.f32 %0, %1;" : "=r"(u) : "f"(x));
    return __uint_as_float(u);
}

// ---------------- kernel 0: gumbel-softmax gate + zero BN stats ----------------
__global__ void probs_kernel(const float* __restrict__ alpha,
                             const float* __restrict__ gumbels,
                             const int* __restrict__ es) {
    int t = threadIdx.x;
    if (t < NCLASS) { g_sum[t] = 0.f; g_ssq[t] = 0.f; }
    if (t == 0) {
        float ws[8];
        float m = -1e30f;
        #pragma unroll
        for (int i = 0; i < 8; i++) { ws[i] = alpha[es[i]]; m = fmaxf(m, ws[i]); }
        float se = 0.f;
        #pragma unroll
        for (int i = 0; i < 8; i++) se += expf(ws[i] - m);
        float lse = m + logf(se);
        float lg[8];
        float m2 = -1e30f;
        #pragma unroll
        for (int i = 0; i < 8; i++) {
            lg[i] = (ws[i] - lse + gumbels[i]) / TAU_F;
            m2 = fmaxf(m2, lg[i]);
        }
        float s2 = 0.f;
        #pragma unroll
        for (int i = 0; i < 8; i++) { lg[i] = expf(lg[i] - m2); s2 += lg[i]; }
        #pragma unroll
        for (int i = 0; i < 8; i++) g_probs[i] = lg[i] / s2;
    }
}

// ------ kernel 1: hybrid tensor+FFMA segmented GEMM + PReLU + GEMM2 + stats ----
__global__ __launch_bounds__(THREADS, 1)
void gemm1_kernel(GemmParams p, const float* __restrict__ prelu_ptr,
                  const float* __restrict__ w_out, float* __restrict__ z) {
    extern __shared__ float smem[];
    float* sh_h = smem;               // epilogue [128][132]
    float* sh_w = smem + WS_OFF;      // epilogue [128][68]

    __shared__ float s_sum[NCLASS];
    __shared__ float s_ssq[NCLASS];

    const int tid = threadIdx.x;
    const int wid = tid >> 5, lane = tid & 31;
    const bool is_tensor = (wid < 12);
    const int wm = wid / 6, wn = wid % 6;      // tensor grid 2 x 6
    const int g = lane >> 2, t4 = lane & 3;
    const int ffrow = (wid - 12) * 32 + lane;  // ffma: one row per thread
    const int row0 = blockIdx.x * BM;

    if (tid < NCLASS) { s_sum[tid] = 0.f; s_ssq[tid] = 0.f; }

    // 64 accumulators, shared storage between roles:
    //   tensor: acc[(t*4+u)*4 + i] ; ffma: acc[c], c = local col 0..63
    float acc[64];
    #pragma unroll
    for (int i = 0; i < 64; i++) acc[i] = 0.f;

    float  ra[8];
    float4 rb[4];

    const int a_off[2] = {A0_OFF, A1_OFF};
    const int b_off[2] = {B0_OFF, B1_OFF};

    auto load_regs = [&](int cs, int k0) {
        const float* __restrict__ A = p.A[cs];
        const float* __restrict__ B = p.B[cs];
        const int d = p.d[cs];
        const float pc = g_probs[cs];
        const int ka = k0 + (tid & 31);
        const int rbase = tid >> 5;
        const bool kok = (ka < d);
        #pragma unroll
        for (int l = 0; l < 8; l++) {
            int row = row0 + rbase + l * 16;
            ra[l] = (kok && row < N_ROWS) ? A[(long)row * d + ka] : 0.f;
        }
        #pragma unroll
        for (int l = 0; l < 4; l++) {
            int flat = l * THREADS + tid;
            int kk = flat >> 6, n4 = flat & 63;
            int k = k0 + kk;
            float4 v = make_float4(0.f, 0.f, 0.f, 0.f);
            if (k < d) v = *(const float4*)(B + (long)k * HIDDEN + n4 * 4);
            v.x *= pc; v.y *= pc; v.z *= pc; v.w *= pc;
            rb[l] = v;
        }
    };

    auto store_tiles = [&](int buf) {
        float* As = smem + a_off[buf];
        float* Bs = smem + b_off[buf];
        const int rbase = tid >> 5;
        const int ka = tid & 31;
        #pragma unroll
        for (int l = 0; l < 8; l++)
            As[(rbase + l * 16) * AS_STRIDE + ka] = f2tf32(ra[l]);
        #pragma unroll
        for (int l = 0; l < 4; l++) {
            int flat = l * THREADS + tid;
            int kk = flat >> 6, n4 = flat & 63;
            float4 v = rb[l];
            float4 w4 = make_float4(f2tf32(v.x), f2tf32(v.y), f2tf32(v.z), f2tf32(v.w));
            *(float4*)&Bs[kk * BS_STRIDE + n4 * 4] = w4;
        }
    };

    auto compute_tensor = [&](int buf) {
        const float* As = smem + a_off[buf];
        const float* Bs = smem + b_off[buf];
        #pragma unroll
        for (int ks = 0; ks < 4; ks++) {
            const int kk = ks * 8;
            uint32_t a[4][4];
            #pragma unroll
            for (int t = 0; t < 4; t++) {
                int base = (wm * 64 + t * 16 + g) * AS_STRIDE + kk + t4;
                a[t][0] = __float_as_uint(As[base]);
                a[t][1] = __float_as_uint(As[base + 8 * AS_STRIDE]);
                a[t][2] = __float_as_uint(As[base + 4]);
                a[t][3] = __float_as_uint(As[base + 8 * AS_STRIDE + 4]);
            }
            uint32_t b[4][2];
            #pragma unroll
            for (int u = 0; u < 4; u++) {
                int base = (kk + t4) * BS_STRIDE + wn * 32 + u * 8 + g;
                b[u][0] = __float_as_uint(Bs[base]);
                b[u][1] = __float_as_uint(Bs[base + 4 * BS_STRIDE]);
            }
            #pragma unroll
            for (int t = 0; t < 4; t++)
                #pragma unroll
                for (int u = 0; u < 4; u++)
                    asm volatile(
                        "mma.sync.aligned.m16n8k8.row.col.f32.tf32.tf32.f32 "
                        "{%0,%1,%2,%3}, {%4,%5,%6,%7}, {%8,%9}, {%0,%1,%2,%3};\n"
                        : "+f"(acc[(t * 4 + u) * 4 + 0]), "+f"(acc[(t * 4 + u) * 4 + 1]),
                          "+f"(acc[(t * 4 + u) * 4 + 2]), "+f"(acc[(t * 4 + u) * 4 + 3])
                        : "r"(a[t][0]), "r"(a[t][1]), "r"(a[t][2]), "r"(a[t][3]),
                          "r"(b[u][0]), "r"(b[u][1]));
        }
    };

    // ffma: k-outer, B loaded in groups of 4 float4 (<=17 live temps)
    auto compute_ffma = [&](int buf) {
        const float* arow = smem + a_off[buf] + ffrow * AS_STRIDE;
        const float* bbase = smem + b_off[buf] + NT_COLS;
        #pragma unroll 8
        for (int k = 0; k < 32; k++) {
            float a = arow[k];
            const float* brow = bbase + k * BS_STRIDE;
            #pragma unroll
            for (int q4 = 0; q4 < 4; q4++) {
                float4 b0 = *(const float4*)&brow[q4 * 16 + 0];
                float4 b1 = *(const float4*)&brow[q4 * 16 + 4];
                float4 b2 = *(const float4*)&brow[q4 * 16 + 8];
                float4 b3 = *(const float4*)&brow[q4 * 16 + 12];
                float* ac = acc + q4 * 16;
                ac[0]  = fmaf(a, b0.x, ac[0]);
                ac[1]  = fmaf(a, b0.y, ac[1]);
                ac[2]  = fmaf(a, b0.z, ac[2]);
                ac[3]  = fmaf(a, b0.w, ac[3]);
                ac[4]  = fmaf(a, b1.x, ac[4]);
                ac[5]  = fmaf(a, b1.y, ac[5]);
                ac[6]  = fmaf(a, b1.z, ac[6]);
                ac[7]  = fmaf(a, b1.w, ac[7]);
                ac[8]  = fmaf(a, b2.x, ac[8]);
                ac[9]  = fmaf(a, b2.y, ac[9]);
                ac[10] = fmaf(a, b2.z, ac[10]);
                ac[11] = fmaf(a, b2.w, ac[11]);
                ac[12] = fmaf(a, b3.x, ac[12]);
                ac[13] = fmaf(a, b3.y, ac[13]);
                ac[14] = fmaf(a, b3.z, ac[14]);
                ac[15] = fmaf(a, b3.w, ac[15]);
            }
        }
    };

    // -------- mainloop: double-buffered, one __syncthreads per chunk --------
    int total = 0;
    #pragma unroll
    for (int c = 0; c < 8; c++) total += (p.d[c] + BK - 1) / BK;   // 86

    int lcs = 0, lk0 = 0;
    auto advance = [&]() { lk0 += BK; if (lk0 >= p.d[lcs]) { lk0 = 0; ++lcs; } };

    load_regs(lcs, lk0);
    store_tiles(0);
    advance();
    if (1 < total) load_regs(lcs, lk0);
    __syncthreads();

    for (int chunk = 0;; chunk++) {
        const int buf = chunk & 1;
        const bool have_next = (chunk + 1 < total);
        if (have_next) {
            store_tiles(buf ^ 1);
            advance();
            if (chunk + 2 < total) load_regs(lcs, lk0);
        }
        if (is_tensor) compute_tensor(buf);
        else           compute_ffma(buf);
        __syncthreads();
        if (!have_next) break;
    }

    // -------- epilogue: PReLU + z = h @ w_out^T (two 128-col K halves) --------
    const float pa = *prelu_ptr;
    float accz[4][4];
    #pragma unroll
    for (int i = 0; i < 4; i++)
        #pragma unroll
        for (int j = 0; j < 4; j++) accz[i][j] = 0.f;

    const int rg = tid >> 4;   // rows rg*4..+3
    const int cg = tid & 15;   // classes cg*4..+3

    #pragma unroll
    for (int kh = 0; kh < 2; kh++) {
        if (is_tensor) {
            const bool mine = (kh == 0) ? (wn < 4) : (wn >= 4);
            if (mine) {
                const int cbase = (kh == 0) ? wn * 32 : (wn - 4) * 32;
                #pragma unroll
                for (int t = 0; t < 4; t++) {
                    const int r1 = wm * 64 + t * 16 + g;
                    #pragma unroll
                    for (int u = 0; u < 4; u++) {
                        const int col = cbase + u * 8 + t4 * 2;
                        float x0 = acc[(t * 4 + u) * 4 + 0], x1 = acc[(t * 4 + u) * 4 + 1];
                        float x2 = acc[(t * 4 + u) * 4 + 2], x3 = acc[(t * 4 + u) * 4 + 3];
                        float2 h01 = make_float2(x0 >= 0.f ? x0 : pa * x0,
                                                 x1 >= 0.f ? x1 : pa * x1);
                        float2 h23 = make_float2(x2 >= 0.f ? x2 : pa * x2,
                                                 x3 >= 0.f ? x3 : pa * x3);
                        *(float2*)&sh_h[r1 * HS_STRIDE + col] = h01;
                        *(float2*)&sh_h[(r1 + 8) * HS_STRIDE + col] = h23;
                    }
                }
            }
        } else if (kh == 1) {
            #pragma unroll
            for (int q = 0; q < 16; q++) {
                float x0 = acc[q * 4 + 0], x1 = acc[q * 4 + 1];
                float x2 = acc[q * 4 + 2], x3 = acc[q * 4 + 3];
                float4 v;
                v.x = (x0 >= 0.f) ? x0 : pa * x0;
                v.y = (x1 >= 0.f) ? x1 : pa * x1;
                v.z = (x2 >= 0.f) ? x2 : pa * x2;
                v.w = (x3 >= 0.f) ? x3 : pa * x3;
                *(float4*)&sh_h[ffrow * HS_STRIDE + 64 + q * 4] = v;
            }
        }
        #pragma unroll
        for (int l = 0; l < 4; l++) {
            int flat = l * THREADS + tid;
            int c = flat & 63, kq = flat >> 6;
            float4 wv = *(const float4*)(w_out + (long)c * HIDDEN + kh * 128 + kq * 4);
            sh_w[(kq * 4 + 0) * WS_STRIDE + c] = wv.x;
            sh_w[(kq * 4 + 1) * WS_STRIDE + c] = wv.y;
            sh_w[(kq * 4 + 2) * WS_STRIDE + c] = wv.z;
            sh_w[(kq * 4 + 3) * WS_STRIDE + c] = wv.w;
        }
        __syncthreads();
        #pragma unroll 8
        for (int k = 0; k < 128; k++) {
            float a0 = sh_h[(rg * 4 + 0) * HS_STRIDE + k];
            float a1 = sh_h[(rg * 4 + 1) * HS_STRIDE + k];
            float a2 = sh_h[(rg * 4 + 2) * HS_STRIDE + k];
            float a3 = sh_h[(rg * 4 + 3) * HS_STRIDE + k];
            float4 wv = *(float4*)&sh_w[k * WS_STRIDE + cg * 4];
            accz[0][0] = fmaf(a0, wv.x, accz[0][0]);
            accz[0][1] = fmaf(a0, wv.y, accz[0][1]);
            accz[0][2] = fmaf(a0, wv.z, accz[0][2]);
            accz[0][3] = fmaf(a0, wv.w, accz[0][3]);
            accz[1][0] = fmaf(a1, wv.x, accz[1][0]);
            accz[1][1] = fmaf(a1, wv.y, accz[1][1]);
            accz[1][2] = fmaf(a1, wv.z, accz[1][2]);
            accz[1][3] = fmaf(a1, wv.w, accz[1][3]);
            accz[2][0] = fmaf(a2, wv.x, accz[2][0]);
            accz[2][1] = fmaf(a2, wv.y, accz[2][1]);
            accz[2][2] = fmaf(a2, wv.z, accz[2][2]);
            accz[2][3] = fmaf(a2, wv.w, accz[2][3]);
            accz[3][0] = fmaf(a3, wv.x, accz[3][0]);
            accz[3][1] = fmaf(a3, wv.y, accz[3][1]);
            accz[3][2] = fmaf(a3, wv.z, accz[3][2]);
            accz[3][3] = fmaf(a3, wv.w, accz[3][3]);
        }
        __syncthreads();
    }

    // -------- write z + BN partial stats --------
    float s[4] = {0.f, 0.f, 0.f, 0.f};
    float q[4] = {0.f, 0.f, 0.f, 0.f};
    #pragma unroll
    for (int i = 0; i < 4; i++) {
        int row = row0 + rg * 4 + i;
        if (row < N_ROWS) {
            float4 v = make_float4(accz[i][0], accz[i][1], accz[i][2], accz[i][3]);
            *(float4*)&z[(long)row * NCLASS + cg * 4] = v;
            s[0] += v.x; q[0] += v.x * v.x;
            s[1] += v.y; q[1] += v.y * v.y;
            s[2] += v.z; q[2] += v.z * v.z;
            s[3] += v.w; q[3] += v.w * v.w;
        }
    }
    #pragma unroll
    for (int j = 0; j < 4; j++) {
        atomicAdd(&s_sum[cg * 4 + j], s[j]);
        atomicAdd(&s_ssq[cg * 4 + j], q[j]);
    }
    __syncthreads();
    if (tid < NCLASS) {
        atomicAdd(&g_sum[tid], s_sum[tid]);
        atomicAdd(&g_ssq[tid], s_ssq[tid]);
    }
}

// ---------------- kernel 2: batchnorm normalize in place ----------------
__global__ __launch_bounds__(256) void bn_kernel(float* __restrict__ z) {
    __shared__ float mean_s[NCLASS];
    __shared__ float rstd_s[NCLASS];
    int t = threadIdx.x;
    if (t < NCLASS) {
        float m = g_sum[t] * (1.0f / (float)N_ROWS);
        float v = g_ssq[t] * (1.0f / (float)N_ROWS) - m * m;
        mean_s[t] = m;
        rstd_s[t] = rsqrtf(v + BN_EPS);
    }
    __syncthreads();
    const size_t nq = (size_t)N_ROWS * NCLASS / 4;
    const size_t stride = (size_t)gridDim.x * blockDim.x;
    size_t i0 = (size_t)blockIdx.x * blockDim.x + t;
    int c = (int)((i0 * 4) & (NCLASS - 1));
    float m0 = mean_s[c], m1 = mean_s[c + 1], m2 = mean_s[c + 2], m3 = mean_s[c + 3];
    float r0 = rstd_s[c], r1 = rstd_s[c + 1], r2 = rstd_s[c + 2], r3 = rstd_s[c + 3];
    for (size_t i = i0; i < nq; i += stride) {
        float4 v = ((float4*)z)[i];
        v.x = (v.x - m0) * r0;
        v.y = (v.y - m1) * r1;
        v.z = (v.z - m2) * r2;
        v.w = (v.w - m3) * r3;
        ((float4*)z)[i] = v;
    }
}

// ---------------- host launcher ----------------
extern "C" void kernel_launch(void* const* d_in, const int* in_sizes, int n_in,
                              void* d_out, int out_size) {
    static const long dims[6] = {334, 512, 128, 745, 256, 600};
    const float* feat[8] = {0};
    const float* emb[8]  = {0};
    const float* alpha = 0;
    const float* gumbels = 0;
    const float* prelu_a = 0;
    const float* w_out = 0;
    const int* es = 0;
    int labc = 0, l16 = 0, c8 = 0;

    for (int i = 0; i < n_in; i++) {
        long s = (long)in_sizes[i];
        const void* ptr = d_in[i];
        bool matched = false;
        for (int k = 0; k < 6; k++) {
            if (s == 100000L * dims[k] && !feat[k]) { feat[k] = (const float*)ptr; matched = true; break; }
            if (s == dims[k] * 256L    && !emb[k])  { emb[k]  = (const float*)ptr; matched = true; break; }
        }
        if (matched) continue;
        if (s == 6400000L) {
            if (labc < 2) feat[6 + labc] = (const float*)ptr;
            labc++;
        } else if (s == 16384L) {
            if (l16 < 2) emb[6 + l16] = (const float*)ptr;
            else w_out = (const float*)ptr;
            l16++;
        } else if (s == 8L) {
            if (c8 == 0) alpha = (const float*)ptr;
            else if (c8 == 1) gumbels = (const float*)ptr;
            else es = (const int*)ptr;
            c8++;
        } else if (s == 1L) {
            prelu_a = (const float*)ptr;
        }
    }

    GemmParams gp;
    for (int c = 0; c < 8; c++) {
        gp.A[c] = feat[c];
        gp.B[c] = emb[c];
        gp.d[c] = (c < 6) ? (int)dims[c] : NCLASS;
    }

    float* z = (float*)d_out;
    const int grid1 = (N_ROWS + BM - 1) / BM;   // 782

    static int attr_set = 0;
    if (!attr_set) {
        cudaFuncSetAttribute(gemm1_kernel,
                             cudaFuncAttributeMaxDynamicSharedMemorySize, SMEM_BYTES);
        attr_set = 1;
    }

    probs_kernel<<<1, 128>>>(alpha, gumbels, es);
    gemm1_kernel<<<grid1, THREADS, SMEM_BYTES>>>(gp, prelu_a, w_out, z);
    bn_kernel<<<1024, 256>>>(z);
}

// round 11
// speedup vs baseline: 2.8405x; 1.9006x over previous
#include <cuda_runtime.h>
#include <math.h>
#include <stdint.h>

#define N_ROWS 100000
#define HIDDEN 256
#define NCLASS 64
#define TAU_F 1.0f
#define BN_EPS 1e-5f

#define BM 128
#define BK 32
#define THREADS 512
#define AS_STRIDE 36
#define BS_STRIDE 264
#define HS_STRIDE 132
#define WS_STRIDE 68

// double-buffered mainloop smem (floats):
//   As0 @0 (4608), Bs0 @4608 (8448), As1 @13056 (4608), Bs1 @17664 (8448)
// epilogue aliases: sh_h @0 (16896), sh_w @16896 (8704)
#define A0_OFF 0
#define B0_OFF 4608
#define A1_OFF 13056
#define B1_OFF 17664
#define WS_OFF 16896
#define SMEM_BYTES 104448

// ---------------- device scratch ----------------
__device__ float g_probs[8];
__device__ float g_sum[NCLASS];
__device__ float g_ssq[NCLASS];

struct GemmParams {
    const float* A[8];   // feat0..5, lab0, lab1   [N, d]
    const float* B[8];   // emb0..5, lemb0, lemb1  [d, 256]
    int d[8];
};

__device__ __forceinline__ float f2tf32(float x) {
    uint32_t u;
    asm("cvt.rna.tf32.f32 %0, %1;" : "=r"(u) : "f"(x));
    return __uint_as_float(u);
}

// ---------------- kernel 0: gumbel-softmax gate + zero BN stats ----------------
__global__ void probs_kernel(const float* __restrict__ alpha,
                             const float* __restrict__ gumbels,
                             const int* __restrict__ es) {
    int t = threadIdx.x;
    if (t < NCLASS) { g_sum[t] = 0.f; g_ssq[t] = 0.f; }
    if (t == 0) {
        float ws[8];
        float m = -1e30f;
        #pragma unroll
        for (int i = 0; i < 8; i++) { ws[i] = alpha[es[i]]; m = fmaxf(m, ws[i]); }
        float se = 0.f;
        #pragma unroll
        for (int i = 0; i < 8; i++) se += expf(ws[i] - m);
        float lse = m + logf(se);
        float lg[8];
        float m2 = -1e30f;
        #pragma unroll
        for (int i = 0; i < 8; i++) {
            lg[i] = (ws[i] - lse + gumbels[i]) / TAU_F;
            m2 = fmaxf(m2, lg[i]);
        }
        float s2 = 0.f;
        #pragma unroll
        for (int i = 0; i < 8; i++) { lg[i] = expf(lg[i] - m2); s2 += lg[i]; }
        #pragma unroll
        for (int i = 0; i < 8; i++) g_probs[i] = lg[i] / s2;
    }
}

// -------- kernel 1: tf32-MMA segmented GEMM + PReLU + tf32-MMA GEMM2 + stats ----
__global__ __launch_bounds__(THREADS, 1)
void gemm1_kernel(GemmParams p, const float* __restrict__ prelu_ptr,
                  const float* __restrict__ w_out, float* __restrict__ z) {
    extern __shared__ float smem[];
    float* sh_h = smem;               // epilogue [128][132] (tf32 bits)
    float* sh_w = smem + WS_OFF;      // epilogue [128][68]  (tf32 bits, k-major)

    __shared__ float s_sum[NCLASS];
    __shared__ float s_ssq[NCLASS];

    const int tid = threadIdx.x;
    const int wid = tid >> 5, lane = tid & 31;
    const int wm = wid >> 3, wn = wid & 7;     // GEMM1 warp grid 2 x 8
    const int g = lane >> 2, t4 = lane & 3;
    const int row0 = blockIdx.x * BM;

    if (tid < NCLASS) { s_sum[tid] = 0.f; s_ssq[tid] = 0.f; }

    float acc[4][4][4];
    #pragma unroll
    for (int t = 0; t < 4; t++)
        #pragma unroll
        for (int u = 0; u < 4; u++)
            #pragma unroll
            for (int i = 0; i < 4; i++) acc[t][u][i] = 0.f;

    float  ra[8];
    float4 rb[4];

    const int a_off[2] = {A0_OFF, A1_OFF};
    const int b_off[2] = {B0_OFF, B1_OFF};

    auto load_regs = [&](int cs, int k0) {
        const float* __restrict__ A = p.A[cs];
        const float* __restrict__ B = p.B[cs];
        const int d = p.d[cs];
        const float pc = g_probs[cs];
        const int ka = k0 + (tid & 31);
        const int rbase = tid >> 5;
        const bool kok = (ka < d);
        #pragma unroll
        for (int l = 0; l < 8; l++) {
            int row = row0 + rbase + l * 16;
            ra[l] = (kok && row < N_ROWS) ? A[(long)row * d + ka] : 0.f;
        }
        #pragma unroll
        for (int l = 0; l < 4; l++) {
            int flat = l * THREADS + tid;
            int kk = flat >> 6, n4 = flat & 63;
            int k = k0 + kk;
            float4 v = make_float4(0.f, 0.f, 0.f, 0.f);
            if (k < d) v = *(const float4*)(B + (long)k * HIDDEN + n4 * 4);
            v.x *= pc; v.y *= pc; v.z *= pc; v.w *= pc;
            rb[l] = v;
        }
    };

    auto store_tiles = [&](int buf) {
        float* As = smem + a_off[buf];
        float* Bs = smem + b_off[buf];
        const int rbase = tid >> 5;
        const int ka = tid & 31;
        #pragma unroll
        for (int l = 0; l < 8; l++)
            As[(rbase + l * 16) * AS_STRIDE + ka] = f2tf32(ra[l]);
        #pragma unroll
        for (int l = 0; l < 4; l++) {
            int flat = l * THREADS + tid;
            int kk = flat >> 6, n4 = flat & 63;
            float4 v = rb[l];
            float4 w4 = make_float4(f2tf32(v.x), f2tf32(v.y), f2tf32(v.z), f2tf32(v.w));
            *(float4*)&Bs[kk * BS_STRIDE + n4 * 4] = w4;
        }
    };

    auto compute_chunk = [&](int buf) {
        const float* As = smem + a_off[buf];
        const float* Bs = smem + b_off[buf];
        #pragma unroll
        for (int ks = 0; ks < 4; ks++) {
            const int kk = ks * 8;
            uint32_t a[4][4];
            #pragma unroll
            for (int t = 0; t < 4; t++) {
                int base = (wm * 64 + t * 16 + g) * AS_STRIDE + kk + t4;
                a[t][0] = __float_as_uint(As[base]);
                a[t][1] = __float_as_uint(As[base + 8 * AS_STRIDE]);
                a[t][2] = __float_as_uint(As[base + 4]);
                a[t][3] = __float_as_uint(As[base + 8 * AS_STRIDE + 4]);
            }
            uint32_t b[4][2];
            #pragma unroll
            for (int u = 0; u < 4; u++) {
                int base = (kk + t4) * BS_STRIDE + wn * 32 + u * 8 + g;
                b[u][0] = __float_as_uint(Bs[base]);
                b[u][1] = __float_as_uint(Bs[base + 4 * BS_STRIDE]);
            }
            #pragma unroll
            for (int t = 0; t < 4; t++)
                #pragma unroll
                for (int u = 0; u < 4; u++)
                    asm volatile(
                        "mma.sync.aligned.m16n8k8.row.col.f32.tf32.tf32.f32 "
                        "{%0,%1,%2,%3}, {%4,%5,%6,%7}, {%8,%9}, {%0,%1,%2,%3};\n"
                        : "+f"(acc[t][u][0]), "+f"(acc[t][u][1]),
                          "+f"(acc[t][u][2]), "+f"(acc[t][u][3])
                        : "r"(a[t][0]), "r"(a[t][1]), "r"(a[t][2]), "r"(a[t][3]),
                          "r"(b[u][0]), "r"(b[u][1]));
        }
    };

    // -------- mainloop: double-buffered, one __syncthreads per chunk --------
    int total = 0;
    #pragma unroll
    for (int c = 0; c < 8; c++) total += (p.d[c] + BK - 1) / BK;   // 86

    int lcs = 0, lk0 = 0;
    auto advance = [&]() { lk0 += BK; if (lk0 >= p.d[lcs]) { lk0 = 0; ++lcs; } };

    load_regs(lcs, lk0);
    store_tiles(0);
    advance();
    if (1 < total) load_regs(lcs, lk0);
    __syncthreads();

    for (int chunk = 0;; chunk++) {
        const int buf = chunk & 1;
        const bool have_next = (chunk + 1 < total);
        if (have_next) {
            store_tiles(buf ^ 1);
            advance();
            if (chunk + 2 < total) load_regs(lcs, lk0);
        }
        compute_chunk(buf);
        __syncthreads();
        if (!have_next) break;
    }

    // ---- epilogue: PReLU (-> tf32 sh_h) + GEMM2 on tensor mma, 2 K-halves ----
    const float pa = *prelu_ptr;
    float accz[16];
    #pragma unroll
    for (int i = 0; i < 16; i++) accz[i] = 0.f;

    const int wm2 = wid >> 1;    // 0..7  M-tile (16 rows)
    const int wn2 = wid & 1;     // 0..1  col group (32 classes)

    #pragma unroll
    for (int kh = 0; kh < 2; kh++) {
        // stage PReLU(x) (tf32-rounded) for hidden cols of this half
        if ((wn >> 2) == kh) {
            const int cbase = (wn & 3) * 32;
            #pragma unroll
            for (int t = 0; t < 4; t++) {
                const int r1 = wm * 64 + t * 16 + g;
                #pragma unroll
                for (int u = 0; u < 4; u++) {
                    const int col = cbase + u * 8 + t4 * 2;
                    float x0 = acc[t][u][0], x1 = acc[t][u][1];
                    float x2 = acc[t][u][2], x3 = acc[t][u][3];
                    float2 h01 = make_float2(f2tf32(x0 >= 0.f ? x0 : pa * x0),
                                             f2tf32(x1 >= 0.f ? x1 : pa * x1));
                    float2 h23 = make_float2(f2tf32(x2 >= 0.f ? x2 : pa * x2),
                                             f2tf32(x3 >= 0.f ? x3 : pa * x3));
                    *(float2*)&sh_h[r1 * HS_STRIDE + col] = h01;
                    *(float2*)&sh_h[(r1 + 8) * HS_STRIDE + col] = h23;
                }
            }
        }
        // stage w_out[:, kh*128 : +128] k-major (tf32-rounded)
        #pragma unroll
        for (int l = 0; l < 4; l++) {
            int flat = l * THREADS + tid;
            int c = flat & 63, kq = flat >> 6;
            float4 wv = *(const float4*)(w_out + (long)c * HIDDEN + kh * 128 + kq * 4);
            sh_w[(kq * 4 + 0) * WS_STRIDE + c] = f2tf32(wv.x);
            sh_w[(kq * 4 + 1) * WS_STRIDE + c] = f2tf32(wv.y);
            sh_w[(kq * 4 + 2) * WS_STRIDE + c] = f2tf32(wv.z);
            sh_w[(kq * 4 + 3) * WS_STRIDE + c] = f2tf32(wv.w);
        }
        __syncthreads();

        // GEMM2 mma: each warp = M-tile wm2 (16 rows) x 32 classes (wn2)
        #pragma unroll
        for (int ks = 0; ks < 16; ks++) {
            const int kk = ks * 8;
            uint32_t a[4];
            const int abase = (wm2 * 16 + g) * HS_STRIDE + kk + t4;
            a[0] = __float_as_uint(sh_h[abase]);
            a[1] = __float_as_uint(sh_h[abase + 8 * HS_STRIDE]);
            a[2] = __float_as_uint(sh_h[abase + 4]);
            a[3] = __float_as_uint(sh_h[abase + 8 * HS_STRIDE + 4]);
            #pragma unroll
            for (int u = 0; u < 4; u++) {
                const int bbase = (kk + t4) * WS_STRIDE + wn2 * 32 + u * 8 + g;
                uint32_t b0 = __float_as_uint(sh_w[bbase]);
                uint32_t b1 = __float_as_uint(sh_w[bbase + 4 * WS_STRIDE]);
                asm volatile(
                    "mma.sync.aligned.m16n8k8.row.col.f32.tf32.tf32.f32 "
                    "{%0,%1,%2,%3}, {%4,%5,%6,%7}, {%8,%9}, {%0,%1,%2,%3};\n"
                    : "+f"(accz[u * 4 + 0]), "+f"(accz[u * 4 + 1]),
                      "+f"(accz[u * 4 + 2]), "+f"(accz[u * 4 + 3])
                    : "r"(a[0]), "r"(a[1]), "r"(a[2]), "r"(a[3]),
                      "r"(b0), "r"(b1));
            }
        }
        __syncthreads();
    }

    // -------- write z + BN partial stats (mma D layout) --------
    const int row_a = row0 + wm2 * 16 + g;
    const int row_b = row_a + 8;
    const bool va = row_a < N_ROWS, vb = row_b < N_ROWS;
    #pragma unroll
    for (int u = 0; u < 4; u++) {
        const int c0 = wn2 * 32 + u * 8 + t4 * 2;
        float d0 = accz[u * 4 + 0], d1 = accz[u * 4 + 1];
        float d2 = accz[u * 4 + 2], d3 = accz[u * 4 + 3];
        if (va) *(float2*)&z[(long)row_a * NCLASS + c0] = make_float2(d0, d1);
        if (vb) *(float2*)&z[(long)row_b * NCLASS + c0] = make_float2(d2, d3);
        float s0 = (va ? d0 : 0.f) + (vb ? d2 : 0.f);
        float q0 = (va ? d0 * d0 : 0.f) + (vb ? d2 * d2 : 0.f);
        float s1 = (va ? d1 : 0.f) + (vb ? d3 : 0.f);
        float q1 = (va ? d1 * d1 : 0.f) + (vb ? d3 * d3 : 0.f);
        atomicAdd(&s_sum[c0], s0);
        atomicAdd(&s_ssq[c0], q0);
        atomicAdd(&s_sum[c0 + 1], s1);
        atomicAdd(&s_ssq[c0 + 1], q1);
    }
    __syncthreads();
    if (tid < NCLASS) {
        atomicAdd(&g_sum[tid], s_sum[tid]);
        atomicAdd(&g_ssq[tid], s_ssq[tid]);
    }
}

// ---------------- kernel 2: batchnorm normalize in place ----------------
__global__ __launch_bounds__(256) void bn_kernel(float* __restrict__ z) {
    __shared__ float mean_s[NCLASS];
    __shared__ float rstd_s[NCLASS];
    int t = threadIdx.x;
    if (t < NCLASS) {
        float m = g_sum[t] * (1.0f / (float)N_ROWS);
        float v = g_ssq[t] * (1.0f / (float)N_ROWS) - m * m;
        mean_s[t] = m;
        rstd_s[t] = rsqrtf(v + BN_EPS);
    }
    __syncthreads();
    const size_t nq = (size_t)N_ROWS * NCLASS / 4;
    const size_t stride = (size_t)gridDim.x * blockDim.x;
    size_t i0 = (size_t)blockIdx.x * blockDim.x + t;
    int c = (int)((i0 * 4) & (NCLASS - 1));
    float m0 = mean_s[c], m1 = mean_s[c + 1], m2 = mean_s[c + 2], m3 = mean_s[c + 3];
    float r0 = rstd_s[c], r1 = rstd_s[c + 1], r2 = rstd_s[c + 2], r3 = rstd_s[c + 3];
    for (size_t i = i0; i < nq; i += stride) {
        float4 v = ((float4*)z)[i];
        v.x = (v.x - m0) * r0;
        v.y = (v.y - m1) * r1;
        v.z = (v.z - m2) * r2;
        v.w = (v.w - m3) * r3;
        ((float4*)z)[i] = v;
    }
}

// ---------------- host launcher ----------------
extern "C" void kernel_launch(void* const* d_in, const int* in_sizes, int n_in,
                              void* d_out, int out_size) {
    static const long dims[6] = {334, 512, 128, 745, 256, 600};
    const float* feat[8] = {0};
    const float* emb[8]  = {0};
    const float* alpha = 0;
    const float* gumbels = 0;
    const float* prelu_a = 0;
    const float* w_out = 0;
    const int* es = 0;
    int labc = 0, l16 = 0, c8 = 0;

    for (int i = 0; i < n_in; i++) {
        long s = (long)in_sizes[i];
        const void* ptr = d_in[i];
        bool matched = false;
        for (int k = 0; k < 6; k++) {
            if (s == 100000L * dims[k] && !feat[k]) { feat[k] = (const float*)ptr; matched = true; break; }
            if (s == dims[k] * 256L    && !emb[k])  { emb[k]  = (const float*)ptr; matched = true; break; }
        }
        if (matched) continue;
        if (s == 6400000L) {
            if (labc < 2) feat[6 + labc] = (const float*)ptr;
            labc++;
        } else if (s == 16384L) {
            if (l16 < 2) emb[6 + l16] = (const float*)ptr;
            else w_out = (const float*)ptr;
            l16++;
        } else if (s == 8L) {
            if (c8 == 0) alpha = (const float*)ptr;
            else if (c8 == 1) gumbels = (const float*)ptr;
            else es = (const int*)ptr;
            c8++;
        } else if (s == 1L) {
            prelu_a = (const float*)ptr;
        }
    }

    GemmParams gp;
    for (int c = 0; c < 8; c++) {
        gp.A[c] = feat[c];
        gp.B[c] = emb[c];
        gp.d[c] = (c < 6) ? (int)dims[c] : NCLASS;
    }

    float* z = (float*)d_out;
    const int grid1 = (N_ROWS + BM - 1) / BM;   // 782

    static int attr_set = 0;
    if (!attr_set) {
        cudaFuncSetAttribute(gemm1_kernel,
                             cudaFuncAttributeMaxDynamicSharedMemorySize, SMEM_BYTES);
        attr_set = 1;
    }

    probs_kernel<<<1, 128>>>(alpha, gumbels, es);
    gemm1_kernel<<<grid1, THREADS, SMEM_BYTES>>>(gp, prelu_a, w_out, z);
    bn_kernel<<<1024, 256>>>(z);
}